// round 13
// baseline (speedup 1.0000x reference)
#include <cuda_runtime.h>
#include <cuda_fp16.h>
#include <cstdint>

// ============================================================
// EdgeUpdate fused MLP via legacy mma.sync (sm_103 non-'a' target).
// R13 = R12 (persistent W1 B-fragments in registers, 64-row tiles,
//   4 warps x (64 rows x 32 cols)) with a REGISTER DIET to reach
//   3 CTAs/SM (<=170 regs): GEMM1 processed in four 16-row
//   quarters (acc 16 regs), GEMM2 in two 32-row halves (acc2 16).
//   Same SMEM/L1 traffic; more concurrent CTAs to de-serialize
//   the gather/tensor/MUFU phases.
// ============================================================

#define XSTR 400   // 192 f16 + 16B pad
#define HSTR 272   // 128 f16 + 16B pad

#define SO_X   0                       // 64 x XSTR = 25600
#define SO_W2  25600                   // 64 x HSTR = 17408
#define SO_H   (SO_W2 + 64 * HSTR)     // 43008
#define SO_B1  (SO_H + 64 * HSTR)      // 60416
#define SO_B2  (SO_B1 + 512)           // 60928
#define SMEM_TOTAL (SO_B2 + 256 + 128) // 61312 B -> 3 CTAs/SM

__device__ __forceinline__ uint32_t s2u(const void* p) {
    uint32_t a;
    asm("{ .reg .u64 t; cvta.to.shared.u64 t, %1; cvt.u32.u64 %0, t; }"
        : "=r"(a) : "l"(p));
    return a;
}

__device__ __forceinline__ uint32_t pkh2(float lo, float hi) {
    uint32_t r;
    asm("cvt.rn.f16x2.f32 %0, %1, %2;" : "=r"(r) : "f"(hi), "f"(lo));
    return r;
}

__device__ __forceinline__ void ldm4(uint32_t* r, uint32_t addr) {
    asm volatile("ldmatrix.sync.aligned.m8n8.x4.shared.b16 {%0,%1,%2,%3}, [%4];"
                 : "=r"(r[0]), "=r"(r[1]), "=r"(r[2]), "=r"(r[3]) : "r"(addr));
}

__device__ __forceinline__ void mma16816(float* d, const uint32_t* a,
                                         uint32_t b0, uint32_t b1) {
    asm volatile(
        "mma.sync.aligned.m16n8k16.row.col.f32.f16.f16.f32 "
        "{%0,%1,%2,%3}, {%4,%5,%6,%7}, {%8,%9}, {%0,%1,%2,%3};"
        : "+f"(d[0]), "+f"(d[1]), "+f"(d[2]), "+f"(d[3])
        : "r"(a[0]), "r"(a[1]), "r"(a[2]), "r"(a[3]), "r"(b0), "r"(b1));
}

// shifted softplus: softplus(x) - ln2 = max(x,0) + ln(1+e^{-|x|}) - ln2
__device__ __forceinline__ float ssp(float x) {
    float e = __expf(-fabsf(x));
    float l = __log2f(1.0f + e);
    return fmaxf(x, 0.0f) + 0.6931471805599453f * (l - 1.0f);
}

__global__ void __launch_bounds__(128, 3)
edge_update_kernel(const float* __restrict__ edge_state,
                   const int* __restrict__ edges,
                   const float* __restrict__ node_state,
                   const float* __restrict__ W1, const float* __restrict__ b1,
                   const float* __restrict__ W2, const float* __restrict__ b2,
                   float* __restrict__ out, int E) {
    extern __shared__ __align__(128) char smem[];
    uint32_t sb = s2u(smem);
    int tid = threadIdx.x;
    int lane = tid & 31, w = tid >> 5;

    // ---- one-time: stage W2 (f32 -> f16) + biases into SMEM ----
    for (int i = tid; i < 64 * 128; i += 128) {
        int n = i >> 7, k = i & 127;
        *(half*)(smem + SO_W2 + n * HSTR + k * 2) = __float2half_rn(W2[i]);
    }
    ((float*)(smem + SO_B1))[tid] = b1[tid];
    if (tid < 64) ((float*)(smem + SO_B2))[tid] = b2[tid];

    // warp tiling: 1m x 4n over 64x128 (GEMM1); GEMM2 n = 16/warp
    const int n0  = w * 32;
    const int n02 = w * 16;

    // ---- one-time: build persistent W1 B-fragments from global ----
    const int fl = lane >> 2;
    const int fk = 2 * (lane & 3);
    uint32_t Bf[12][2][4];
#pragma unroll
    for (int k = 0; k < 12; k++) {
#pragma unroll
        for (int g = 0; g < 2; g++) {
            const float* p0 = W1 + (n0 + 16 * g + fl) * 192 + 16 * k + fk;
            const float* p1 = p0 + 8 * 192;
            Bf[k][g][0] = pkh2(p0[0], p0[1]);
            Bf[k][g][1] = pkh2(p0[8], p0[9]);
            Bf[k][g][2] = pkh2(p1[0], p1[1]);
            Bf[k][g][3] = pkh2(p1[8], p1[9]);
        }
    }
    __syncthreads();

    // per-lane bias pairs (loop-invariant)
    float2 b1v[4], b2v[2];
    {
        const float* b1s = (const float*)(smem + SO_B1);
        const float* b2s = (const float*)(smem + SO_B2);
        int cb = 2 * (lane & 3);
#pragma unroll
        for (int nt = 0; nt < 4; nt++)
            b1v[nt] = *(const float2*)(b1s + n0 + nt * 8 + cb);
#pragma unroll
        for (int h = 0; h < 2; h++)
            b2v[h] = *(const float2*)(b2s + n02 + h * 8 + cb);
    }

    // ldmatrix per-lane address components
    const int a_r = lane & 15;
    const int a_c = (lane >> 4) << 3;
    const int b_r = ((lane >> 4) << 3) + (lane & 7);
    const int b_c = ((lane >> 3) & 1) << 3;

    const uint32_t aX0 = sb + SO_X + (uint32_t)a_r * XSTR + a_c * 2;
    const uint32_t aH0 = sb + SO_H + (uint32_t)a_r * HSTR + a_c * 2;
    const uint32_t bW2 = sb + SO_W2 + (uint32_t)(n02 + b_r) * HSTR + b_c * 2;

    const int act_r = lane >> 2;
    const int act_c = 2 * (lane & 3);

    // gather lane mapping: half-warp per row, lane li owns float4 #li
    const int g_half = lane >> 4;
    const int g_li   = lane & 15;

    int ntiles = (E + 63) >> 6;
    for (int t = blockIdx.x; t < ntiles; t += gridDim.x) {
        // ========== coalesced gather -> f16 X tile (64 rows) ==========
#pragma unroll
        for (int it = 0; it < 8; it++) {
            int row = w * 16 + it * 2 + g_half;
            long long e = (long long)t * 64 + row;
            long long ec = (e < E) ? e : (long long)(E - 1);
            int2 np2 = ((const int2*)edges)[ec];
            uint32_t xr = sb + SO_X + (uint32_t)row * XSTR + (uint32_t)g_li * 8u;
            float4 v0 = ((const float4*)(node_state + (long long)np2.x * 64))[g_li];
            float4 v1 = ((const float4*)(node_state + (long long)np2.y * 64))[g_li];
            float4 v2 = __ldcs((const float4*)(edge_state + ec * 64) + g_li);
            uint32_t a0 = pkh2(v0.x, v0.y), a1 = pkh2(v0.z, v0.w);
            uint32_t c0 = pkh2(v1.x, v1.y), c1 = pkh2(v1.z, v1.w);
            uint32_t d0 = pkh2(v2.x, v2.y), d1 = pkh2(v2.z, v2.w);
            asm volatile("st.shared.v2.b32 [%0], {%1,%2};"
                         :: "r"(xr), "r"(a0), "r"(a1) : "memory");
            asm volatile("st.shared.v2.b32 [%0], {%1,%2};"
                         :: "r"(xr + 128), "r"(c0), "r"(c1) : "memory");
            asm volatile("st.shared.v2.b32 [%0], {%1,%2};"
                         :: "r"(xr + 256), "r"(d0), "r"(d1) : "memory");
        }
        __syncthreads();

        // ====== GEMM1 + act, four 16-row quarters (acc = 16 regs) ======
#pragma unroll
        for (int q4 = 0; q4 < 4; q4++) {
            float acc[4][4];
#pragma unroll
            for (int nt = 0; nt < 4; nt++)
#pragma unroll
                for (int q = 0; q < 4; q++) acc[nt][q] = 0.0f;

            uint32_t aXq = aX0 + (uint32_t)(q4 * 16) * XSTR;
#pragma unroll
            for (int k = 0; k < 12; k++) {
                uint32_t Am[4];
                ldm4(Am, aXq + k * 32);
#pragma unroll
                for (int g = 0; g < 2; g++) {
                    mma16816(acc[2 * g],     Am, Bf[k][g][0], Bf[k][g][1]);
                    mma16816(acc[2 * g + 1], Am, Bf[k][g][2], Bf[k][g][3]);
                }
            }

            // act for rows q4*16 + {act_r, act_r+8}
            uint32_t ha = sb + SO_H
                        + (uint32_t)(q4 * 16 + act_r) * HSTR
                        + (uint32_t)(n0 + act_c) * 2;
#pragma unroll
            for (int nt = 0; nt < 4; nt++) {
                float x0 = acc[nt][0] + b1v[nt].x;
                float x1 = acc[nt][1] + b1v[nt].y;
                float x2 = acc[nt][2] + b1v[nt].x;
                float x3 = acc[nt][3] + b1v[nt].y;
                uint32_t h01 = pkh2(ssp(x0), ssp(x1));
                uint32_t h23 = pkh2(ssp(x2), ssp(x3));
                asm volatile("st.shared.b32 [%0], %1;"
                             :: "r"(ha + nt * 16), "r"(h01) : "memory");
                asm volatile("st.shared.b32 [%0], %1;"
                             :: "r"(ha + nt * 16 + 8 * HSTR), "r"(h23) : "memory");
            }
        }
        __syncthreads();

        // ====== GEMM2 + epilogue, two 32-row halves (acc2 = 16 regs) ======
#pragma unroll
        for (int mh = 0; mh < 2; mh++) {
            float acc2[2][2][4];
#pragma unroll
            for (int mt = 0; mt < 2; mt++)
#pragma unroll
                for (int h = 0; h < 2; h++)
#pragma unroll
                    for (int q = 0; q < 4; q++) acc2[mt][h][q] = 0.0f;

            uint32_t aHh = aH0 + (uint32_t)(mh * 32) * HSTR;
#pragma unroll
            for (int k = 0; k < 8; k++) {
                uint32_t Am0[4], Am1[4], B2[4];
                ldm4(Am0, aHh + k * 32);
                ldm4(Am1, aHh + 16 * HSTR + k * 32);
                ldm4(B2, bW2 + k * 32);
                mma16816(acc2[0][0], Am0, B2[0], B2[1]);
                mma16816(acc2[0][1], Am0, B2[2], B2[3]);
                mma16816(acc2[1][0], Am1, B2[0], B2[1]);
                mma16816(acc2[1][1], Am1, B2[2], B2[3]);
            }

            long long ebase = (long long)t * 64 + mh * 32 + act_r;
#pragma unroll
            for (int mt = 0; mt < 2; mt++) {
                long long r0e = ebase + mt * 16;
#pragma unroll
                for (int h = 0; h < 2; h++) {
                    int c = n02 + h * 8 + act_c;
                    if (r0e < E) {
                        float2 v;
                        v.x = acc2[mt][h][0] + b2v[h].x;
                        v.y = acc2[mt][h][1] + b2v[h].y;
                        __stcs((float2*)(out + r0e * 64 + c), v);
                    }
                    if (r0e + 8 < E) {
                        float2 v;
                        v.x = acc2[mt][h][2] + b2v[h].x;
                        v.y = acc2[mt][h][3] + b2v[h].y;
                        __stcs((float2*)(out + (r0e + 8) * 64 + c), v);
                    }
                }
            }
        }
        // no trailing sync: next gather writes only X (all GEMM1 X-reads
        // completed before the H-sync above); H rewrites are ordered after
        // GEMM2 reads by the next tile's gather-sync.
    }
}

extern "C" void kernel_launch(void* const* d_in, const int* in_sizes, int n_in,
                              void* d_out, int out_size) {
    const float* edge_state = (const float*)d_in[0];
    const int*   edges      = (const int*)d_in[1];
    const float* node_state = (const float*)d_in[2];
    const float* W1         = (const float*)d_in[3];
    const float* b1         = (const float*)d_in[4];
    const float* W2         = (const float*)d_in[5];
    const float* b2         = (const float*)d_in[6];
    float*       out        = (float*)d_out;
    int E = in_sizes[0] / 64;

    cudaFuncSetAttribute(edge_update_kernel,
                         cudaFuncAttributeMaxDynamicSharedMemorySize, SMEM_TOTAL);
    edge_update_kernel<<<444, 128, SMEM_TOTAL>>>(edge_state, edges, node_state,
                                                 W1, b1, W2, b2, out, E);
}

// round 14
// speedup vs baseline: 1.0785x; 1.0785x over previous
#include <cuda_runtime.h>
#include <cuda_fp16.h>
#include <cstdint>

// ============================================================
// EdgeUpdate fused MLP via legacy mma.sync (sm_103 non-'a' target).
// R14 = three proven mechanisms combined:
//   * W1 B-fragments persistent in registers (R12 win: -30% L1)
//   * producer warps + double-buffered X (R6: gather off the
//     consumer critical path)
//   * 2 CTAs/SM (R5: the only phase-overlap that ever helped)
// 192-thread CTAs: warps 0-3 consumers (quartered GEMM1+act, two-
// half GEMM2; regs <= 170), warps 4-5 producers (gather).
// One bar.sync(0,192) per tile + consumer-only bar.sync(1,128).
// ============================================================

#define XSTR 400   // 192 f16 + 16B pad
#define HSTR 272   // 128 f16 + 16B pad
#define XBUF (64 * XSTR)               // 25600 per X buffer

#define SO_X0  0
#define SO_X1  XBUF                    // 25600
#define SO_W2  (2 * XBUF)              // 51200
#define SO_H   (SO_W2 + 64 * HSTR)     // 68608
#define SO_B1  (SO_H + 64 * HSTR)      // 86016
#define SO_B2  (SO_B1 + 512)           // 86528
#define SMEM_TOTAL (SO_B2 + 256 + 128) // ~86.9 KB -> 2 CTAs/SM

#define BARX(id, cnt) \
    asm volatile("bar.sync %0, %1;" :: "r"(id), "r"(cnt) : "memory")

__device__ __forceinline__ uint32_t s2u(const void* p) {
    uint32_t a;
    asm("{ .reg .u64 t; cvta.to.shared.u64 t, %1; cvt.u32.u64 %0, t; }"
        : "=r"(a) : "l"(p));
    return a;
}

__device__ __forceinline__ uint32_t pkh2(float lo, float hi) {
    uint32_t r;
    asm("cvt.rn.f16x2.f32 %0, %1, %2;" : "=r"(r) : "f"(hi), "f"(lo));
    return r;
}

__device__ __forceinline__ void ldm4(uint32_t* r, uint32_t addr) {
    asm volatile("ldmatrix.sync.aligned.m8n8.x4.shared.b16 {%0,%1,%2,%3}, [%4];"
                 : "=r"(r[0]), "=r"(r[1]), "=r"(r[2]), "=r"(r[3]) : "r"(addr));
}

__device__ __forceinline__ void mma16816(float* d, const uint32_t* a,
                                         uint32_t b0, uint32_t b1) {
    asm volatile(
        "mma.sync.aligned.m16n8k16.row.col.f32.f16.f16.f32 "
        "{%0,%1,%2,%3}, {%4,%5,%6,%7}, {%8,%9}, {%0,%1,%2,%3};"
        : "+f"(d[0]), "+f"(d[1]), "+f"(d[2]), "+f"(d[3])
        : "r"(a[0]), "r"(a[1]), "r"(a[2]), "r"(a[3]), "r"(b0), "r"(b1));
}

// shifted softplus: softplus(x) - ln2 = max(x,0) + ln(1+e^{-|x|}) - ln2
__device__ __forceinline__ float ssp(float x) {
    float e = __expf(-fabsf(x));
    float l = __log2f(1.0f + e);
    return fmaxf(x, 0.0f) + 0.6931471805599453f * (l - 1.0f);
}

// producer warp pw (0/1) fills rows [32pw, 32pw+32) of X buffer xb
__device__ __forceinline__ void fill32(
    uint32_t xb, long long tile, int pw, int g_half, int g_li,
    const int* __restrict__ edges, const float* __restrict__ node_state,
    const float* __restrict__ edge_state, int E) {
#pragma unroll 4
    for (int i2 = 0; i2 < 16; i2++) {
        int row = pw * 32 + i2 * 2 + g_half;
        long long e = tile * 64 + row;
        long long ec = (e < E) ? e : (long long)(E - 1);
        int2 np2 = ((const int2*)edges)[ec];
        uint32_t xr = xb + (uint32_t)row * XSTR + (uint32_t)g_li * 8u;
        float4 v0 = ((const float4*)(node_state + (long long)np2.x * 64))[g_li];
        float4 v1 = ((const float4*)(node_state + (long long)np2.y * 64))[g_li];
        float4 v2 = __ldcs((const float4*)(edge_state + ec * 64) + g_li);
        uint32_t a0 = pkh2(v0.x, v0.y), a1 = pkh2(v0.z, v0.w);
        uint32_t c0 = pkh2(v1.x, v1.y), c1 = pkh2(v1.z, v1.w);
        uint32_t d0 = pkh2(v2.x, v2.y), d1 = pkh2(v2.z, v2.w);
        asm volatile("st.shared.v2.b32 [%0], {%1,%2};"
                     :: "r"(xr), "r"(a0), "r"(a1) : "memory");
        asm volatile("st.shared.v2.b32 [%0], {%1,%2};"
                     :: "r"(xr + 128), "r"(c0), "r"(c1) : "memory");
        asm volatile("st.shared.v2.b32 [%0], {%1,%2};"
                     :: "r"(xr + 256), "r"(d0), "r"(d1) : "memory");
    }
}

__global__ void __launch_bounds__(192, 2)
edge_update_kernel(const float* __restrict__ edge_state,
                   const int* __restrict__ edges,
                   const float* __restrict__ node_state,
                   const float* __restrict__ W1, const float* __restrict__ b1,
                   const float* __restrict__ W2, const float* __restrict__ b2,
                   float* __restrict__ out, int E) {
    extern __shared__ __align__(128) char smem[];
    uint32_t sb = s2u(smem);
    int tid = threadIdx.x;
    int lane = tid & 31, w = tid >> 5;

    // ---- one-time: stage W2 (f32 -> f16) + biases into SMEM ----
    for (int i = tid; i < 64 * 128; i += 192) {
        int n = i >> 7, k = i & 127;
        *(half*)(smem + SO_W2 + n * HSTR + k * 2) = __float2half_rn(W2[i]);
    }
    if (tid < 128) ((float*)(smem + SO_B1))[tid] = b1[tid];
    if (tid < 64)  ((float*)(smem + SO_B2))[tid] = b2[tid];

    const int ntiles = (E + 63) >> 6;
    const int g_half = lane >> 4;
    const int g_li   = lane & 15;

    // ---- consumer-only: persistent W1 B-fragments from global ----
    const int n0  = (w & 3) * 32;    // consumer GEMM1 cols
    const int n02 = (w & 3) * 16;    // consumer GEMM2 cols
    uint32_t Bf[12][2][4];
    if (w < 4) {
        const int fl = lane >> 2;
        const int fk = 2 * (lane & 3);
#pragma unroll
        for (int k = 0; k < 12; k++) {
#pragma unroll
            for (int g = 0; g < 2; g++) {
                const float* p0 = W1 + (n0 + 16 * g + fl) * 192 + 16 * k + fk;
                const float* p1 = p0 + 8 * 192;
                Bf[k][g][0] = pkh2(p0[0], p0[1]);
                Bf[k][g][1] = pkh2(p0[8], p0[9]);
                Bf[k][g][2] = pkh2(p1[0], p1[1]);
                Bf[k][g][3] = pkh2(p1[8], p1[9]);
            }
        }
    }
    BARX(0, 192);   // staging + Bf visible

    if (w >= 4) {
        // =================== PRODUCERS (warps 4-5) ===================
        const int pw = w - 4;
        long long t0 = blockIdx.x;
        if (t0 < ntiles)
            fill32(sb + SO_X0, t0, pw, g_half, g_li, edges, node_state,
                   edge_state, E);
        int it = 0;
        for (long long t = t0; t < ntiles; t += gridDim.x, it++) {
            BARX(0, 192);   // buf[it&1] published; buf[(it+1)&1] free
            long long tn = t + gridDim.x;
            if (tn < ntiles)
                fill32(sb + ((it & 1) ? SO_X0 : SO_X1), tn, pw, g_half, g_li,
                       edges, node_state, edge_state, E);
        }
    } else {
        // =================== CONSUMERS (warps 0-3) ===================
        float2 b1v[4], b2v[2];
        {
            const float* b1s = (const float*)(smem + SO_B1);
            const float* b2s = (const float*)(smem + SO_B2);
            int cb = 2 * (lane & 3);
#pragma unroll
            for (int nt = 0; nt < 4; nt++)
                b1v[nt] = *(const float2*)(b1s + n0 + nt * 8 + cb);
#pragma unroll
            for (int h = 0; h < 2; h++)
                b2v[h] = *(const float2*)(b2s + n02 + h * 8 + cb);
        }

        const int a_r = lane & 15;
        const int a_c = (lane >> 4) << 3;
        const int b_r = ((lane >> 4) << 3) + (lane & 7);
        const int b_c = ((lane >> 3) & 1) << 3;

        const uint32_t aXo = (uint32_t)a_r * XSTR + a_c * 2;  // + buffer base
        const uint32_t aH0 = sb + SO_H + (uint32_t)a_r * HSTR + a_c * 2;
        const uint32_t bW2 = sb + SO_W2 + (uint32_t)(n02 + b_r) * HSTR + b_c * 2;

        const int act_r = lane >> 2;
        const int act_c = 2 * (lane & 3);

        int it = 0;
        for (long long t = blockIdx.x; t < ntiles; t += gridDim.x, it++) {
            BARX(0, 192);   // X buf[it&1] ready
            uint32_t xb = sb + ((it & 1) ? SO_X1 : SO_X0);

            // ==== GEMM1 + act, four 16-row quarters (acc = 16 regs) ====
#pragma unroll
            for (int q4 = 0; q4 < 4; q4++) {
                float acc[4][4];
#pragma unroll
                for (int nt = 0; nt < 4; nt++)
#pragma unroll
                    for (int q = 0; q < 4; q++) acc[nt][q] = 0.0f;

                uint32_t aXq = xb + aXo + (uint32_t)(q4 * 16) * XSTR;
#pragma unroll
                for (int k = 0; k < 12; k++) {
                    uint32_t Am[4];
                    ldm4(Am, aXq + k * 32);
#pragma unroll
                    for (int g = 0; g < 2; g++) {
                        mma16816(acc[2 * g],     Am, Bf[k][g][0], Bf[k][g][1]);
                        mma16816(acc[2 * g + 1], Am, Bf[k][g][2], Bf[k][g][3]);
                    }
                }

                uint32_t ha = sb + SO_H
                            + (uint32_t)(q4 * 16 + act_r) * HSTR
                            + (uint32_t)(n0 + act_c) * 2;
#pragma unroll
                for (int nt = 0; nt < 4; nt++) {
                    float x0 = acc[nt][0] + b1v[nt].x;
                    float x1 = acc[nt][1] + b1v[nt].y;
                    float x2 = acc[nt][2] + b1v[nt].x;
                    float x3 = acc[nt][3] + b1v[nt].y;
                    uint32_t h01 = pkh2(ssp(x0), ssp(x1));
                    uint32_t h23 = pkh2(ssp(x2), ssp(x3));
                    asm volatile("st.shared.b32 [%0], %1;"
                                 :: "r"(ha + nt * 16), "r"(h01) : "memory");
                    asm volatile("st.shared.b32 [%0], %1;"
                                 :: "r"(ha + nt * 16 + 8 * HSTR), "r"(h23) : "memory");
                }
            }
            BARX(1, 128);   // consumer-only: H complete

            // ==== GEMM2 + epilogue, two 32-row halves (acc2 = 16 regs) ====
#pragma unroll
            for (int mh = 0; mh < 2; mh++) {
                float acc2[2][2][4];
#pragma unroll
                for (int mt = 0; mt < 2; mt++)
#pragma unroll
                    for (int h = 0; h < 2; h++)
#pragma unroll
                        for (int q = 0; q < 4; q++) acc2[mt][h][q] = 0.0f;

                uint32_t aHh = aH0 + (uint32_t)(mh * 32) * HSTR;
#pragma unroll
                for (int k = 0; k < 8; k++) {
                    uint32_t Am0[4], Am1[4], B2[4];
                    ldm4(Am0, aHh + k * 32);
                    ldm4(Am1, aHh + 16 * HSTR + k * 32);
                    ldm4(B2, bW2 + k * 32);
                    mma16816(acc2[0][0], Am0, B2[0], B2[1]);
                    mma16816(acc2[0][1], Am0, B2[2], B2[3]);
                    mma16816(acc2[1][0], Am1, B2[0], B2[1]);
                    mma16816(acc2[1][1], Am1, B2[2], B2[3]);
                }

                long long ebase = t * 64 + mh * 32 + act_r;
#pragma unroll
                for (int mt = 0; mt < 2; mt++) {
                    long long r0e = ebase + mt * 16;
#pragma unroll
                    for (int h = 0; h < 2; h++) {
                        int c = n02 + h * 8 + act_c;
                        if (r0e < E) {
                            float2 v;
                            v.x = acc2[mt][h][0] + b2v[h].x;
                            v.y = acc2[mt][h][1] + b2v[h].y;
                            __stcs((float2*)(out + r0e * 64 + c), v);
                        }
                        if (r0e + 8 < E) {
                            float2 v;
                            v.x = acc2[mt][h][2] + b2v[h].x;
                            v.y = acc2[mt][h][3] + b2v[h].y;
                            __stcs((float2*)(out + (r0e + 8) * 64 + c), v);
                        }
                    }
                }
            }
            // H rewrite (next tile's act) is ordered after this GEMM2 by
            // the next iteration's BARX(0,192) + the act's position after it.
        }
    }
}

extern "C" void kernel_launch(void* const* d_in, const int* in_sizes, int n_in,
                              void* d_out, int out_size) {
    const float* edge_state = (const float*)d_in[0];
    const int*   edges      = (const int*)d_in[1];
    const float* node_state = (const float*)d_in[2];
    const float* W1         = (const float*)d_in[3];
    const float* b1         = (const float*)d_in[4];
    const float* W2         = (const float*)d_in[5];
    const float* b2         = (const float*)d_in[6];
    float*       out        = (float*)d_out;
    int E = in_sizes[0] / 64;

    cudaFuncSetAttribute(edge_update_kernel,
                         cudaFuncAttributeMaxDynamicSharedMemorySize, SMEM_TOTAL);
    edge_update_kernel<<<296, 192, SMEM_TOTAL>>>(edge_state, edges, node_state,
                                                 W1, b1, W2, b2, out, E);
}

// round 15
// speedup vs baseline: 1.1038x; 1.0235x over previous
#include <cuda_runtime.h>
#include <cuda_fp16.h>
#include <cstdint>

// ============================================================
// EdgeUpdate fused MLP via legacy mma.sync (sm_103 non-'a' target).
// R15 = R14 (W1 B-frags in registers + producer warps + double-
//   buffered X + 2 CTAs/SM) + node_state pre-converted to f16 ONCE
//   by a small first kernel into __device__ scratch. Producers read
//   8B/lane uint2 node rows (half the L2 gather bytes) and skip
//   fp32->f16 packing for node data.
// ============================================================

#define XSTR 400   // 192 f16 + 16B pad
#define HSTR 272   // 128 f16 + 16B pad
#define XBUF (64 * XSTR)               // 25600 per X buffer

#define SO_X0  0
#define SO_X1  XBUF                    // 25600
#define SO_W2  (2 * XBUF)              // 51200
#define SO_H   (SO_W2 + 64 * HSTR)     // 68608
#define SO_B1  (SO_H + 64 * HSTR)      // 86016
#define SO_B2  (SO_B1 + 512)           // 86528
#define SMEM_TOTAL (SO_B2 + 256 + 128) // ~86.9 KB -> 2 CTAs/SM

#define BARX(id, cnt) \
    asm volatile("bar.sync %0, %1;" :: "r"(id), "r"(cnt) : "memory")

// f16 copy of node_state (100000 x 64); filled by conv kernel each call
static __device__ __align__(16) __half g_ns16[6400000];

__device__ __forceinline__ uint32_t s2u(const void* p) {
    uint32_t a;
    asm("{ .reg .u64 t; cvta.to.shared.u64 t, %1; cvt.u32.u64 %0, t; }"
        : "=r"(a) : "l"(p));
    return a;
}

__device__ __forceinline__ uint32_t pkh2(float lo, float hi) {
    uint32_t r;
    asm("cvt.rn.f16x2.f32 %0, %1, %2;" : "=r"(r) : "f"(hi), "f"(lo));
    return r;
}

__device__ __forceinline__ void ldm4(uint32_t* r, uint32_t addr) {
    asm volatile("ldmatrix.sync.aligned.m8n8.x4.shared.b16 {%0,%1,%2,%3}, [%4];"
                 : "=r"(r[0]), "=r"(r[1]), "=r"(r[2]), "=r"(r[3]) : "r"(addr));
}

__device__ __forceinline__ void mma16816(float* d, const uint32_t* a,
                                         uint32_t b0, uint32_t b1) {
    asm volatile(
        "mma.sync.aligned.m16n8k16.row.col.f32.f16.f16.f32 "
        "{%0,%1,%2,%3}, {%4,%5,%6,%7}, {%8,%9}, {%0,%1,%2,%3};"
        : "+f"(d[0]), "+f"(d[1]), "+f"(d[2]), "+f"(d[3])
        : "r"(a[0]), "r"(a[1]), "r"(a[2]), "r"(a[3]), "r"(b0), "r"(b1));
}

// shifted softplus: softplus(x) - ln2 = max(x,0) + ln(1+e^{-|x|}) - ln2
__device__ __forceinline__ float ssp(float x) {
    float e = __expf(-fabsf(x));
    float l = __log2f(1.0f + e);
    return fmaxf(x, 0.0f) + 0.6931471805599453f * (l - 1.0f);
}

// ---------- kernel 1: node_state fp32 -> f16 ----------
__global__ void conv_nodes_kernel(const float4* __restrict__ ns, int n4) {
    int i = blockIdx.x * blockDim.x + threadIdx.x;
    if (i < n4) {
        float4 v = ns[i];
        uint2 o;
        o.x = pkh2(v.x, v.y);
        o.y = pkh2(v.z, v.w);
        ((uint2*)g_ns16)[i] = o;
    }
}

// producer warp pw (0/1) fills rows [32pw, 32pw+32) of X buffer xb
__device__ __forceinline__ void fill32(
    uint32_t xb, long long tile, int pw, int g_half, int g_li,
    const int* __restrict__ edges,
    const float* __restrict__ edge_state, int E) {
#pragma unroll 4
    for (int i2 = 0; i2 < 16; i2++) {
        int row = pw * 32 + i2 * 2 + g_half;
        long long e = tile * 64 + row;
        long long ec = (e < E) ? e : (long long)(E - 1);
        int2 np2 = ((const int2*)edges)[ec];
        uint32_t xr = xb + (uint32_t)row * XSTR + (uint32_t)g_li * 8u;
        // node rows already f16: 8B per lane
        uint2 v0 = ((const uint2*)(g_ns16 + (long long)np2.x * 64))[g_li];
        uint2 v1 = ((const uint2*)(g_ns16 + (long long)np2.y * 64))[g_li];
        float4 v2 = __ldcs((const float4*)(edge_state + ec * 64) + g_li);
        uint32_t d0 = pkh2(v2.x, v2.y), d1 = pkh2(v2.z, v2.w);
        asm volatile("st.shared.v2.b32 [%0], {%1,%2};"
                     :: "r"(xr), "r"(v0.x), "r"(v0.y) : "memory");
        asm volatile("st.shared.v2.b32 [%0], {%1,%2};"
                     :: "r"(xr + 128), "r"(v1.x), "r"(v1.y) : "memory");
        asm volatile("st.shared.v2.b32 [%0], {%1,%2};"
                     :: "r"(xr + 256), "r"(d0), "r"(d1) : "memory");
    }
}

__global__ void __launch_bounds__(192, 2)
edge_update_kernel(const float* __restrict__ edge_state,
                   const int* __restrict__ edges,
                   const float* __restrict__ W1, const float* __restrict__ b1,
                   const float* __restrict__ W2, const float* __restrict__ b2,
                   float* __restrict__ out, int E) {
    extern __shared__ __align__(128) char smem[];
    uint32_t sb = s2u(smem);
    int tid = threadIdx.x;
    int lane = tid & 31, w = tid >> 5;

    // ---- one-time: stage W2 (f32 -> f16) + biases into SMEM ----
    for (int i = tid; i < 64 * 128; i += 192) {
        int n = i >> 7, k = i & 127;
        *(half*)(smem + SO_W2 + n * HSTR + k * 2) = __float2half_rn(W2[i]);
    }
    if (tid < 128) ((float*)(smem + SO_B1))[tid] = b1[tid];
    if (tid < 64)  ((float*)(smem + SO_B2))[tid] = b2[tid];

    const int ntiles = (E + 63) >> 6;
    const int g_half = lane >> 4;
    const int g_li   = lane & 15;

    // ---- consumer-only: persistent W1 B-fragments from global ----
    const int n0  = (w & 3) * 32;    // consumer GEMM1 cols
    const int n02 = (w & 3) * 16;    // consumer GEMM2 cols
    uint32_t Bf[12][2][4];
    if (w < 4) {
        const int fl = lane >> 2;
        const int fk = 2 * (lane & 3);
#pragma unroll
        for (int k = 0; k < 12; k++) {
#pragma unroll
            for (int g = 0; g < 2; g++) {
                const float* p0 = W1 + (n0 + 16 * g + fl) * 192 + 16 * k + fk;
                const float* p1 = p0 + 8 * 192;
                Bf[k][g][0] = pkh2(p0[0], p0[1]);
                Bf[k][g][1] = pkh2(p0[8], p0[9]);
                Bf[k][g][2] = pkh2(p1[0], p1[1]);
                Bf[k][g][3] = pkh2(p1[8], p1[9]);
            }
        }
    }
    BARX(0, 192);   // staging + Bf visible

    if (w >= 4) {
        // =================== PRODUCERS (warps 4-5) ===================
        const int pw = w - 4;
        long long t0 = blockIdx.x;
        if (t0 < ntiles)
            fill32(sb + SO_X0, t0, pw, g_half, g_li, edges, edge_state, E);
        int it = 0;
        for (long long t = t0; t < ntiles; t += gridDim.x, it++) {
            BARX(0, 192);   // buf[it&1] published; buf[(it+1)&1] free
            long long tn = t + gridDim.x;
            if (tn < ntiles)
                fill32(sb + ((it & 1) ? SO_X0 : SO_X1), tn, pw, g_half, g_li,
                       edges, edge_state, E);
        }
    } else {
        // =================== CONSUMERS (warps 0-3) ===================
        float2 b1v[4], b2v[2];
        {
            const float* b1s = (const float*)(smem + SO_B1);
            const float* b2s = (const float*)(smem + SO_B2);
            int cb = 2 * (lane & 3);
#pragma unroll
            for (int nt = 0; nt < 4; nt++)
                b1v[nt] = *(const float2*)(b1s + n0 + nt * 8 + cb);
#pragma unroll
            for (int h = 0; h < 2; h++)
                b2v[h] = *(const float2*)(b2s + n02 + h * 8 + cb);
        }

        const int a_r = lane & 15;
        const int a_c = (lane >> 4) << 3;
        const int b_r = ((lane >> 4) << 3) + (lane & 7);
        const int b_c = ((lane >> 3) & 1) << 3;

        const uint32_t aXo = (uint32_t)a_r * XSTR + a_c * 2;  // + buffer base
        const uint32_t aH0 = sb + SO_H + (uint32_t)a_r * HSTR + a_c * 2;
        const uint32_t bW2 = sb + SO_W2 + (uint32_t)(n02 + b_r) * HSTR + b_c * 2;

        const int act_r = lane >> 2;
        const int act_c = 2 * (lane & 3);

        int it = 0;
        for (long long t = blockIdx.x; t < ntiles; t += gridDim.x, it++) {
            BARX(0, 192);   // X buf[it&1] ready
            uint32_t xb = sb + ((it & 1) ? SO_X1 : SO_X0);

            // ==== GEMM1 + act, four 16-row quarters (acc = 16 regs) ====
#pragma unroll
            for (int q4 = 0; q4 < 4; q4++) {
                float acc[4][4];
#pragma unroll
                for (int nt = 0; nt < 4; nt++)
#pragma unroll
                    for (int q = 0; q < 4; q++) acc[nt][q] = 0.0f;

                uint32_t aXq = xb + aXo + (uint32_t)(q4 * 16) * XSTR;
#pragma unroll
                for (int k = 0; k < 12; k++) {
                    uint32_t Am[4];
                    ldm4(Am, aXq + k * 32);
#pragma unroll
                    for (int g = 0; g < 2; g++) {
                        mma16816(acc[2 * g],     Am, Bf[k][g][0], Bf[k][g][1]);
                        mma16816(acc[2 * g + 1], Am, Bf[k][g][2], Bf[k][g][3]);
                    }
                }

                uint32_t ha = sb + SO_H
                            + (uint32_t)(q4 * 16 + act_r) * HSTR
                            + (uint32_t)(n0 + act_c) * 2;
#pragma unroll
                for (int nt = 0; nt < 4; nt++) {
                    float x0 = acc[nt][0] + b1v[nt].x;
                    float x1 = acc[nt][1] + b1v[nt].y;
                    float x2 = acc[nt][2] + b1v[nt].x;
                    float x3 = acc[nt][3] + b1v[nt].y;
                    uint32_t h01 = pkh2(ssp(x0), ssp(x1));
                    uint32_t h23 = pkh2(ssp(x2), ssp(x3));
                    asm volatile("st.shared.b32 [%0], %1;"
                                 :: "r"(ha + nt * 16), "r"(h01) : "memory");
                    asm volatile("st.shared.b32 [%0], %1;"
                                 :: "r"(ha + nt * 16 + 8 * HSTR), "r"(h23) : "memory");
                }
            }
            BARX(1, 128);   // consumer-only: H complete

            // ==== GEMM2 + epilogue, two 32-row halves (acc2 = 16 regs) ====
#pragma unroll
            for (int mh = 0; mh < 2; mh++) {
                float acc2[2][2][4];
#pragma unroll
                for (int mt = 0; mt < 2; mt++)
#pragma unroll
                    for (int h = 0; h < 2; h++)
#pragma unroll
                        for (int q = 0; q < 4; q++) acc2[mt][h][q] = 0.0f;

                uint32_t aHh = aH0 + (uint32_t)(mh * 32) * HSTR;
#pragma unroll
                for (int k = 0; k < 8; k++) {
                    uint32_t Am0[4], Am1[4], B2[4];
                    ldm4(Am0, aHh + k * 32);
                    ldm4(Am1, aHh + 16 * HSTR + k * 32);
                    ldm4(B2, bW2 + k * 32);
                    mma16816(acc2[0][0], Am0, B2[0], B2[1]);
                    mma16816(acc2[0][1], Am0, B2[2], B2[3]);
                    mma16816(acc2[1][0], Am1, B2[0], B2[1]);
                    mma16816(acc2[1][1], Am1, B2[2], B2[3]);
                }

                long long ebase = t * 64 + mh * 32 + act_r;
#pragma unroll
                for (int mt = 0; mt < 2; mt++) {
                    long long r0e = ebase + mt * 16;
#pragma unroll
                    for (int h = 0; h < 2; h++) {
                        int c = n02 + h * 8 + act_c;
                        if (r0e < E) {
                            float2 v;
                            v.x = acc2[mt][h][0] + b2v[h].x;
                            v.y = acc2[mt][h][1] + b2v[h].y;
                            __stcs((float2*)(out + r0e * 64 + c), v);
                        }
                        if (r0e + 8 < E) {
                            float2 v;
                            v.x = acc2[mt][h][2] + b2v[h].x;
                            v.y = acc2[mt][h][3] + b2v[h].y;
                            __stcs((float2*)(out + (r0e + 8) * 64 + c), v);
                        }
                    }
                }
            }
        }
    }
}

extern "C" void kernel_launch(void* const* d_in, const int* in_sizes, int n_in,
                              void* d_out, int out_size) {
    const float* edge_state = (const float*)d_in[0];
    const int*   edges      = (const int*)d_in[1];
    const float* node_state = (const float*)d_in[2];
    const float* W1         = (const float*)d_in[3];
    const float* b1         = (const float*)d_in[4];
    const float* W2         = (const float*)d_in[5];
    const float* b2         = (const float*)d_in[6];
    float*       out        = (float*)d_out;
    int E = in_sizes[0] / 64;
    int n4 = in_sizes[2] / 4;    // node_state float4 count

    conv_nodes_kernel<<<(n4 + 255) / 256, 256>>>((const float4*)node_state, n4);

    cudaFuncSetAttribute(edge_update_kernel,
                         cudaFuncAttributeMaxDynamicSharedMemorySize, SMEM_TOTAL);
    edge_update_kernel<<<296, 192, SMEM_TOTAL>>>(edge_state, edges,
                                                 W1, b1, W2, b2, out, E);
}